// round 13
// baseline (speedup 1.0000x reference)
#include <cuda_runtime.h>
#include <cuda_bf16.h>

#define TT 512
#define H 8
#define NSM 148
#define BLK 512
#define SEGS_PER_BLK (BLK / 16)

typedef unsigned long long u64;

__device__ __forceinline__ float tanhf_a(float x) {
    float y; asm("tanh.approx.f32 %0, %1;" : "=f"(y) : "f"(x)); return y;
}
__device__ __forceinline__ u64 pack2(float lo, float hi) {
    u64 r; asm("mov.b64 %0, {%1, %2};" : "=l"(r) : "f"(lo), "f"(hi)); return r;
}
__device__ __forceinline__ void unpack2(u64 v, float& lo, float& hi) {
    asm("mov.b64 {%0, %1}, %2;" : "=f"(lo), "=f"(hi) : "l"(v));
}
__device__ __forceinline__ u64 fma2(u64 a, u64 b, u64 c) {
    u64 r; asm("fma.rn.f32x2 %0, %1, %2, %3;" : "=l"(r) : "l"(a), "l"(b), "l"(c)); return r;
}
__device__ __forceinline__ u64 add2(u64 a, u64 b) {
    u64 r; asm("add.rn.f32x2 %0, %1, %2;" : "=l"(r) : "l"(a), "l"(b)); return r;
}
__device__ __forceinline__ float hsum2(u64 v) {
    float lo, hi; unpack2(v, lo, hi); return lo + hi;
}
__device__ __forceinline__ u64 d2u(double d) {
    return (u64)__double_as_longlong(d);
}

__global__ void __launch_bounds__(BLK, 1)
lstm2_kernel(const float* __restrict__ x,
             const float* __restrict__ W_ih1, const float* __restrict__ W_hh1,
             const float* __restrict__ b_ih1, const float* __restrict__ b_hh1,
             const float* __restrict__ W_ih2, const float* __restrict__ W_hh2,
             const float* __restrict__ b_ih2, const float* __restrict__ b_hh2,
             const float* __restrict__ W_fc,  const float* __restrict__ b_fc,
             float* __restrict__ out, int B)
{
    const int m     = threadIdx.x & 15;                 // lane within 16-lane segment
    const int half  = m >> 3;                           // 0 = layer1 lanes, 1 = layer2 lanes
    const int n     = m & 7;                            // hidden unit of this lane
    const int sg    = threadIdx.x >> 4;                 // segment index in block (0..31)
    const int seg   = blockIdx.x * SEGS_PER_BLK + sg;   // global segment id
    const bool active = (seg < B);
    const int batch = active ? seg : 0;                 // dummy segments replay batch 0

    // ping-pong broadcast buffers: [parity][segment][layer][unit]
    __shared__ __align__(16) float hbuf[2][SEGS_PER_BLK][2][8];

    // sigmoid(z) = 0.5*tanh(0.5*z)+0.5 -> pre-scale sigmoid-gate rows by 0.5
    const float SS = 0.5f, SG = 1.0f;
    const int ri = n, rf = 8 + n, rg = 16 + n, ro = 24 + n;

    // Per-half weight selection (identical code path, different data):
    //  half0 (layer1): a = Whh1 . h1prev + (wx,0...)·(xt,0...) + b1
    //  half1 (layer2): a = Wih2 . h1prev +  Whh2 . h2prev      + b2
    const float* WA  = half ? W_ih2 : W_hh1;
    const float* Bi  = half ? b_ih2 : b_ih1;
    const float* Bh  = half ? b_hh2 : b_hh1;

    const u64 bi = pack2((Bi[ri] + Bh[ri]) * SS, 0.0f);
    const u64 bf = pack2((Bi[rf] + Bh[rf]) * SS, 0.0f);
    const u64 bg = pack2((Bi[rg] + Bh[rg]) * SG, 0.0f);
    const u64 bo = pack2((Bi[ro] + Bh[ro]) * SS, 0.0f);

    u64 wai[4], waf[4], wag[4], wao[4];
    u64 wbi[4], wbf[4], wbg[4], wbo[4];
#pragma unroll
    for (int p = 0; p < 4; ++p) {
        const int k0 = 2*p, k1 = 2*p + 1;
        wai[p] = pack2(WA[ri*H + k0] * SS, WA[ri*H + k1] * SS);
        waf[p] = pack2(WA[rf*H + k0] * SS, WA[rf*H + k1] * SS);
        wag[p] = pack2(WA[rg*H + k0] * SG, WA[rg*H + k1] * SG);
        wao[p] = pack2(WA[ro*H + k0] * SS, WA[ro*H + k1] * SS);
        if (half) {
            wbi[p] = pack2(W_hh2[ri*H + k0] * SS, W_hh2[ri*H + k1] * SS);
            wbf[p] = pack2(W_hh2[rf*H + k0] * SS, W_hh2[rf*H + k1] * SS);
            wbg[p] = pack2(W_hh2[rg*H + k0] * SG, W_hh2[rg*H + k1] * SG);
            wbo[p] = pack2(W_hh2[ro*H + k0] * SS, W_hh2[ro*H + k1] * SS);
        } else if (p == 0) {
            wbi[0] = pack2(W_ih1[ri] * SS, 0.0f);
            wbf[0] = pack2(W_ih1[rf] * SS, 0.0f);
            wbg[0] = pack2(W_ih1[rg] * SG, 0.0f);
            wbo[0] = pack2(W_ih1[ro] * SS, 0.0f);
        } else {
            wbi[p] = 0; wbf[p] = 0; wbg[p] = 0; wbo[p] = 0;
        }
    }

    const u64 Z = pack2(0.0f, 0.0f);
    u64 va[4], hb[4];        // va = h1(t-1) broadcast; hb = h2(prev) broadcast
#pragma unroll
    for (int p = 0; p < 4; ++p) { va[p] = Z; hb[p] = Z; }
    float c = 0.0f;

    // One body: half0 computes layer1 step t; half1 computes layer2 step t-1.
    auto step = [&](float xt, int par) {
        const u64 vb0 = half ? hb[0] : pack2(xt, 0.0f);

        u64 ia = bi, fa = bf, ga = bg, oa = bo;
        u64 ib = Z,  fb = Z,  gb = Z,  ob = Z;
#pragma unroll
        for (int p = 0; p < 4; ++p) {
            const u64 vbp = (p == 0) ? vb0 : hb[p];
            ia = fma2(wai[p], va[p], ia);
            fa = fma2(waf[p], va[p], fa);
            ga = fma2(wag[p], va[p], ga);
            oa = fma2(wao[p], va[p], oa);
            ib = fma2(wbi[p], vbp, ib);
            fb = fma2(wbf[p], vbp, fb);
            gb = fma2(wbg[p], vbp, gb);
            ob = fma2(wbo[p], vbp, ob);
        }
        const float ai = hsum2(add2(ia, ib));
        const float af = hsum2(add2(fa, fb));
        const float ag = hsum2(add2(ga, gb));
        const float ao = hsum2(add2(oa, ob));

        const float gi = fmaf(0.5f, tanhf_a(ai), 0.5f);
        const float gf = fmaf(0.5f, tanhf_a(af), 0.5f);
        const float go = fmaf(0.5f, tanhf_a(ao), 0.5f);
        const float gg = tanhf_a(ag);
        c = fmaf(gf, c, gi * gg);
        const float hn = go * tanhf_a(c);

        // ---- SMEM broadcast: 1 STS + syncwarp + 4 LDS.128 ----
        // half0 lanes publish h1(t) into [sg][0][n]; half1 publish h2 into [sg][1][n]
        hbuf[par][sg][half][n] = hn;
        __syncwarp();
        const double2* pa = (const double2*)&hbuf[par][sg][0][0];
        const double2* pb = (const double2*)&hbuf[par][sg][1][0];
        const double2 a0 = pa[0], a1 = pa[1];
        const double2 b0 = pb[0], b1 = pb[1];
        va[0] = d2u(a0.x); va[1] = d2u(a0.y);
        va[2] = d2u(a1.x); va[3] = d2u(a1.y);
        hb[0] = d2u(b0.x); hb[1] = d2u(b0.y);
        hb[2] = d2u(b1.x); hb[3] = d2u(b1.y);
    };

    const float4* __restrict__ xr = (const float4*)(x + (size_t)batch * TT);
    float4 cur = xr[0];
    float4 nxt = xr[1];

    // prologue: body 0 computes layer1(0); half1's layer2(-1) is junk -> reset
    step(cur.x, 0);
    if (half) c = 0.0f;
#pragma unroll
    for (int p = 0; p < 4; ++p) hb[p] = Z;     // h2(-1) := 0 for body 1

    step(cur.y, 1); step(cur.z, 0); step(cur.w, 1);
    cur = nxt;

    for (int t4 = 1; t4 < TT/4; ++t4) {
        const int nidx = (t4 + 1 < TT/4) ? (t4 + 1) : t4;
        nxt = xr[nidx];
        step(cur.x, 0); step(cur.y, 1); step(cur.z, 0); step(cur.w, 1);
        cur = nxt;
    }

    // epilogue: body 512 computes layer2(511) on half1; half0's layer1(512) junk
    step(0.0f, 0);

    // ---------- final FC (8 -> 4): hb now holds h2(511) on all lanes ----------
    if (active && m < 4) {
        u64 acc = pack2(b_fc[m], 0.0f);
#pragma unroll
        for (int p = 0; p < 4; ++p) {
            const u64 w = pack2(W_fc[m*H + 2*p], W_fc[m*H + 2*p + 1]);
            acc = fma2(w, hb[p], acc);
        }
        out[batch * 4 + m] = hsum2(acc);
    }
}

extern "C" void kernel_launch(void* const* d_in, const int* in_sizes, int n_in,
                              void* d_out, int out_size)
{
    const float* x     = (const float*)d_in[0];
    const float* W_ih1 = (const float*)d_in[1];
    const float* W_hh1 = (const float*)d_in[2];
    const float* b_ih1 = (const float*)d_in[3];
    const float* b_hh1 = (const float*)d_in[4];
    const float* W_ih2 = (const float*)d_in[5];
    const float* W_hh2 = (const float*)d_in[6];
    const float* b_ih2 = (const float*)d_in[7];
    const float* b_hh2 = (const float*)d_in[8];
    const float* W_fc  = (const float*)d_in[9];
    const float* b_fc  = (const float*)d_in[10];
    float* out = (float*)d_out;

    const int B = in_sizes[0] / TT;          // 4096
    // 148 blocks x 512 threads = 2368 warps = exactly 4 warps/SMSP on every SM;
    // 4736 segment slots >= 4096 batches (surplus run dummies)
    int blocks = NSM;
    const int min_blocks = (B * 16 + BLK - 1) / BLK;
    if (blocks < min_blocks) blocks = min_blocks;   // safety for other sizes

    lstm2_kernel<<<blocks, BLK>>>(x, W_ih1, W_hh1, b_ih1, b_hh1,
                                  W_ih2, W_hh2, b_ih2, b_hh2,
                                  W_fc, b_fc, out, B);
}

// round 14
// speedup vs baseline: 1.2138x; 1.2138x over previous
#include <cuda_runtime.h>
#include <cuda_bf16.h>

#define TT 512
#define H 8
#define NSM 148
#define BLK 256
#define GROUPS_PER_BLK (BLK / 8)

typedef unsigned long long u64;

__device__ __forceinline__ float tanhf_a(float x) {
    float y; asm("tanh.approx.f32 %0, %1;" : "=f"(y) : "f"(x)); return y;
}
__device__ __forceinline__ u64 pack2(float lo, float hi) {
    u64 r; asm("mov.b64 %0, {%1, %2};" : "=l"(r) : "f"(lo), "f"(hi)); return r;
}
__device__ __forceinline__ void unpack2(u64 v, float& lo, float& hi) {
    asm("mov.b64 {%0, %1}, %2;" : "=f"(lo), "=f"(hi) : "l"(v));
}
__device__ __forceinline__ u64 fma2(u64 a, u64 b, u64 c) {
    u64 r; asm("fma.rn.f32x2 %0, %1, %2, %3;" : "=l"(r) : "l"(a), "l"(b), "l"(c)); return r;
}
__device__ __forceinline__ u64 mul2(u64 a, u64 b) {
    u64 r; asm("mul.rn.f32x2 %0, %1, %2;" : "=l"(r) : "l"(a), "l"(b)); return r;
}
__device__ __forceinline__ float hsum2(u64 v) {
    float lo, hi; unpack2(v, lo, hi); return lo + hi;
}
__device__ __forceinline__ u64 d2u(double d) {
    return (u64)__double_as_longlong(d);
}

__global__ void __launch_bounds__(BLK, 1)
lstm2_kernel(const float* __restrict__ x,
             const float* __restrict__ W_ih1, const float* __restrict__ W_hh1,
             const float* __restrict__ b_ih1, const float* __restrict__ b_hh1,
             const float* __restrict__ W_ih2, const float* __restrict__ W_hh2,
             const float* __restrict__ b_ih2, const float* __restrict__ b_hh2,
             const float* __restrict__ W_fc,  const float* __restrict__ b_fc,
             float* __restrict__ out, int B)
{
    const int wg    = threadIdx.x >> 3;                      // group in block (0..31)
    const int n     = threadIdx.x & 7;                       // hidden unit of this lane
    const int group = blockIdx.x * GROUPS_PER_BLK + wg;      // global group id
    const bool active = (group < B);
    const int batch = active ? group : 0;                    // dummy groups replay batch 0

    // ping-pong broadcast buffers: [parity][group][layer][unit]
    __shared__ __align__(16) float hbuf[2][GROUPS_PER_BLK][2][8];

    // sigmoid(z) = 0.5*tanh(0.5*z)+0.5 -> pre-scale sigmoid-gate rows by 0.5
    const float SS = 0.5f, SG = 1.0f;
    const int ri = n, rf = 8 + n, rg = 16 + n, ro = 24 + n;
    const u64 HALF2 = pack2(0.5f, 0.5f);

    // layer-1 x weights (scalar; applied post-hsum)
    const float wxi = W_ih1[ri] * SS, wxf = W_ih1[rf] * SS;
    const float wxg = W_ih1[rg] * SG, wxo = W_ih1[ro] * SS;

    // biases packed as (b, 0): they seed the packed accumulator chains
    const u64 bi1 = pack2((b_ih1[ri] + b_hh1[ri]) * SS, 0.0f);
    const u64 bf1 = pack2((b_ih1[rf] + b_hh1[rf]) * SS, 0.0f);
    const u64 bg1 = pack2((b_ih1[rg] + b_hh1[rg]) * SG, 0.0f);
    const u64 bo1 = pack2((b_ih1[ro] + b_hh1[ro]) * SS, 0.0f);
    const u64 bi2 = pack2((b_ih2[ri] + b_hh2[ri]) * SS, 0.0f);
    const u64 bf2 = pack2((b_ih2[rf] + b_hh2[rf]) * SS, 0.0f);
    const u64 bg2 = pack2((b_ih2[rg] + b_hh2[rg]) * SG, 0.0f);
    const u64 bo2 = pack2((b_ih2[ro] + b_hh2[ro]) * SS, 0.0f);

    u64 whi1[4], whf1[4], whg1[4], who1[4];
    u64 wii2[4], wif2[4], wig2[4], wio2[4];
    u64 whi2[4], whf2[4], whg2[4], who2[4];
#pragma unroll
    for (int p = 0; p < 4; ++p) {
        const int k0 = 2*p, k1 = 2*p + 1;
        whi1[p] = pack2(W_hh1[ri*H + k0] * SS, W_hh1[ri*H + k1] * SS);
        whf1[p] = pack2(W_hh1[rf*H + k0] * SS, W_hh1[rf*H + k1] * SS);
        whg1[p] = pack2(W_hh1[rg*H + k0] * SG, W_hh1[rg*H + k1] * SG);
        who1[p] = pack2(W_hh1[ro*H + k0] * SS, W_hh1[ro*H + k1] * SS);
        wii2[p] = pack2(W_ih2[ri*H + k0] * SS, W_ih2[ri*H + k1] * SS);
        wif2[p] = pack2(W_ih2[rf*H + k0] * SS, W_ih2[rf*H + k1] * SS);
        wig2[p] = pack2(W_ih2[rg*H + k0] * SG, W_ih2[rg*H + k1] * SG);
        wio2[p] = pack2(W_ih2[ro*H + k0] * SS, W_ih2[ro*H + k1] * SS);
        whi2[p] = pack2(W_hh2[ri*H + k0] * SS, W_hh2[ri*H + k1] * SS);
        whf2[p] = pack2(W_hh2[rf*H + k0] * SS, W_hh2[rf*H + k1] * SS);
        whg2[p] = pack2(W_hh2[rg*H + k0] * SG, W_hh2[rg*H + k1] * SG);
        who2[p] = pack2(W_hh2[ro*H + k0] * SS, W_hh2[ro*H + k1] * SS);
    }

    const u64 Z = pack2(0.0f, 0.0f);
    u64 h1p[4], h2p[4];           // h1(t-1), h2(t-2) broadcasts (packed pairs)
#pragma unroll
    for (int p = 0; p < 4; ++p) { h1p[p] = Z; h2p[p] = Z; }
    u64 c12 = Z;                  // packed (c1, c2)

    // One pipelined body: layer1(t) [uses h1p, xt] || layer2(t-1) [uses h1p, h2p]
    auto step = [&](float xt, int par) {
        // ---- 8 independent 4/8-deep packed chains, all seeded from biases ----
        u64 vi = bi1, vf = bf1, vg = bg1, vo = bo1;          // layer1 (4-deep)
        u64 ai = bi2, af = bf2, ag = bg2, ao = bo2;          // layer2 (8-deep, merged)
#pragma unroll
        for (int p = 0; p < 4; ++p) {
            vi = fma2(whi1[p], h1p[p], vi);
            vf = fma2(whf1[p], h1p[p], vf);
            vg = fma2(whg1[p], h1p[p], vg);
            vo = fma2(who1[p], h1p[p], vo);
            ai = fma2(wii2[p], h1p[p], ai);
            af = fma2(wif2[p], h1p[p], af);
            ag = fma2(wig2[p], h1p[p], ag);
            ao = fma2(wio2[p], h1p[p], ao);
        }
#pragma unroll
        for (int p = 0; p < 4; ++p) {
            ai = fma2(whi2[p], h2p[p], ai);
            af = fma2(whf2[p], h2p[p], af);
            ag = fma2(whg2[p], h2p[p], ag);
            ao = fma2(who2[p], h2p[p], ao);
        }
        // layer1 activations: x-term folded in post-hsum (scalar FFMA)
        const float a1i = fmaf(wxi, xt, hsum2(vi));
        const float a1f = fmaf(wxf, xt, hsum2(vf));
        const float a1g = fmaf(wxg, xt, hsum2(vg));
        const float a1o = fmaf(wxo, xt, hsum2(vo));
        const float a2i = hsum2(ai);
        const float a2f = hsum2(af);
        const float a2g = hsum2(ag);
        const float a2o = hsum2(ao);

        // 8 gate activations (MUFU), then packed cross-layer tail
        const u64 Pi = pack2(tanhf_a(a1i), tanhf_a(a2i));
        const u64 Pf = pack2(tanhf_a(a1f), tanhf_a(a2f));
        const u64 Po = pack2(tanhf_a(a1o), tanhf_a(a2o));
        const u64 Pg = pack2(tanhf_a(a1g), tanhf_a(a2g));

        const u64 gi2 = fma2(Pi, HALF2, HALF2);
        const u64 gf2 = fma2(Pf, HALF2, HALF2);
        const u64 go2 = fma2(Po, HALF2, HALF2);

        c12 = fma2(gf2, c12, mul2(gi2, Pg));
        float cc1, cc2; unpack2(c12, cc1, cc2);
        const u64 Pc = pack2(tanhf_a(cc1), tanhf_a(cc2));
        const u64 h12 = mul2(go2, Pc);
        float h1n, h2n; unpack2(h12, h1n, h2n);

        // ---- SMEM broadcast: 2 STS + syncwarp + 4 LDS.128 ----
        hbuf[par][wg][0][n] = h1n;
        hbuf[par][wg][1][n] = h2n;
        __syncwarp();
        const double2* pa = (const double2*)&hbuf[par][wg][0][0];
        const double2* pb = (const double2*)&hbuf[par][wg][1][0];
        const double2 a0 = pa[0], a1 = pa[1];
        const double2 b0 = pb[0], b1 = pb[1];
        h1p[0] = d2u(a0.x); h1p[1] = d2u(a0.y);
        h1p[2] = d2u(a1.x); h1p[3] = d2u(a1.y);
        h2p[0] = d2u(b0.x); h2p[1] = d2u(b0.y);
        h2p[2] = d2u(b1.x); h2p[3] = d2u(b1.y);
    };

    const float4* __restrict__ xr = (const float4*)(x + (size_t)batch * TT);
    float4 cur = xr[0];
    float4 nxt = xr[1];

    // prologue: first body computes layer1(0); its layer2(-1) output is junk
    step(cur.x, 0);
    {   // reset layer2 state (keep c1)
        float c1k, cj; unpack2(c12, c1k, cj);
        c12 = pack2(c1k, 0.0f);
    }
#pragma unroll
    for (int p = 0; p < 4; ++p) h2p[p] = Z;

    step(cur.y, 1); step(cur.z, 0); step(cur.w, 1);
    cur = nxt;

    for (int t4 = 1; t4 < TT/4; ++t4) {
        const int nidx = (t4 + 1 < TT/4) ? (t4 + 1) : t4;
        nxt = xr[nidx];
        step(cur.x, 0); step(cur.y, 1); step(cur.z, 0); step(cur.w, 1);
        cur = nxt;
    }

    // epilogue: one more body computes layer2(511); layer1(512) discarded
    step(0.0f, 0);

    // ---------- final FC (8 -> 4): h2p holds broadcast h2(511) ----------
    if (active && n < 4) {
        u64 acc = pack2(b_fc[n], 0.0f);
#pragma unroll
        for (int p = 0; p < 4; ++p) {
            const u64 w = pack2(W_fc[n*H + 2*p], W_fc[n*H + 2*p + 1]);
            acc = fma2(w, h2p[p], acc);
        }
        out[batch * 4 + n] = hsum2(acc);
    }
}

extern "C" void kernel_launch(void* const* d_in, const int* in_sizes, int n_in,
                              void* d_out, int out_size)
{
    const float* x     = (const float*)d_in[0];
    const float* W_ih1 = (const float*)d_in[1];
    const float* W_hh1 = (const float*)d_in[2];
    const float* b_ih1 = (const float*)d_in[3];
    const float* b_hh1 = (const float*)d_in[4];
    const float* W_ih2 = (const float*)d_in[5];
    const float* W_hh2 = (const float*)d_in[6];
    const float* b_ih2 = (const float*)d_in[7];
    const float* b_hh2 = (const float*)d_in[8];
    const float* W_fc  = (const float*)d_in[9];
    const float* b_fc  = (const float*)d_in[10];
    float* out = (float*)d_out;

    const int B = in_sizes[0] / TT;          // 4096
    // balanced grid: 1 block/SM, 2 warps/SMSP everywhere;
    // 148*32 = 4736 group slots >= 4096 batches (surplus run dummies)
    int blocks = NSM;
    const int min_blocks = (B * H + BLK - 1) / BLK;
    if (blocks < min_blocks) blocks = min_blocks;   // safety for other sizes

    lstm2_kernel<<<blocks, BLK>>>(x, W_ih1, W_hh1, b_ih1, b_hh1,
                                  W_ih2, W_hh2, b_ih2, b_hh2,
                                  W_fc, b_fc, out, B);
}